// round 5
// baseline (speedup 1.0000x reference)
#include <cuda_runtime.h>
#include <cuda_bf16.h>
#include <math.h>
#include <stdint.h>

#define BB 8
#define NN 8192
#define SS 2048
#define C1 128
#define C2 256
#define CIN 384
#define H1 256
#define H2 128
#define M_TOTAL (BB * NN)   /* 65536 */
#define BN_EPS 1e-5f

// ================= scratch (static device globals; no allocation) =================
__device__ float g_y[(size_t)M_TOTAL * H1];        // 64 MB GEMM1 out (pre-BN)
__device__ float g_sum1[H1];
__device__ float g_sumsq1[H1];
__device__ float g_sum2[H2];
__device__ float g_sumsq2[H2];
__device__ float g_scale1[H1];
__device__ float g_shift1[H1];
__device__ float g_scale2[H2];
__device__ float g_shift2[H2];
// activations as bf16 hi/lo splits
__device__ __align__(16) __nv_bfloat16 g_A1hi[(size_t)M_TOTAL * CIN];  // 48 MB
__device__ __align__(16) __nv_bfloat16 g_A1lo[(size_t)M_TOTAL * CIN];
__device__ __align__(16) __nv_bfloat16 g_A2hi[(size_t)M_TOTAL * H1];   // 32 MB
__device__ __align__(16) __nv_bfloat16 g_A2lo[(size_t)M_TOTAL * H1];
// weights as [n][k] bf16 hi/lo splits
__device__ __align__(16) __nv_bfloat16 g_W1hi[H1 * CIN];
__device__ __align__(16) __nv_bfloat16 g_W1lo[H1 * CIN];
__device__ __align__(16) __nv_bfloat16 g_W2hi[H2 * H1];
__device__ __align__(16) __nv_bfloat16 g_W2lo[H2 * H1];

// ================= helpers =================
__device__ __forceinline__ uint32_t smem_u32(const void* p) {
    uint32_t a;
    asm("{ .reg .u64 t; cvta.to.shared.u64 t, %1; cvt.u32.u64 %0, t; }" : "=r"(a) : "l"(p));
    return a;
}
__device__ __forceinline__ void ldsm4(uint32_t* r, uint32_t addr) {
    asm volatile("ldmatrix.sync.aligned.m8n8.x4.shared.b16 {%0,%1,%2,%3}, [%4];"
        : "=r"(r[0]), "=r"(r[1]), "=r"(r[2]), "=r"(r[3]) : "r"(addr));
}
__device__ __forceinline__ void ldsm2(uint32_t* r, uint32_t addr) {
    asm volatile("ldmatrix.sync.aligned.m8n8.x2.shared.b16 {%0,%1}, [%2];"
        : "=r"(r[0]), "=r"(r[1]) : "r"(addr));
}
__device__ __forceinline__ void mma_bf16(float* c, const uint32_t* a, const uint32_t* b) {
    asm volatile(
        "mma.sync.aligned.m16n8k16.row.col.f32.bf16.bf16.f32 "
        "{%0,%1,%2,%3}, {%4,%5,%6,%7}, {%8,%9}, {%0,%1,%2,%3};\n"
        : "+f"(c[0]), "+f"(c[1]), "+f"(c[2]), "+f"(c[3])
        : "r"(a[0]), "r"(a[1]), "r"(a[2]), "r"(a[3]), "r"(b[0]), "r"(b[1]));
}
__device__ __forceinline__ void cvt_hilo(float x, __nv_bfloat16& h, __nv_bfloat16& l) {
    h = __float2bfloat16_rn(x);
    l = __float2bfloat16_rn(x - __bfloat162float(h));
}
__device__ __forceinline__ void cp16(uint32_t dst, const void* src) {
    asm volatile("cp.async.cg.shared.global [%0], [%1], 16;" :: "r"(dst), "l"(src));
}
#define CP_COMMIT() asm volatile("cp.async.commit_group;" ::: "memory")
#define CP_WAIT2()  asm volatile("cp.async.wait_group 2;" ::: "memory")

// ================= kernel: zero stats =================
__global__ void zero_stats_kernel() {
    int t = threadIdx.x;
    if (t < H1) { g_sum1[t] = 0.f; g_sumsq1[t] = 0.f; }
    if (t < H2) { g_sum2[t] = 0.f; g_sumsq2[t] = 0.f; }
}

// ================= kernel: weight prep =================
__global__ void prep_weights_kernel(const float* __restrict__ W1, const float* __restrict__ W2) {
    int i = blockIdx.x * blockDim.x + threadIdx.x;
    if (i < H1 * CIN) {
        __nv_bfloat16 h, l;
        cvt_hilo(W1[i], h, l);
        g_W1hi[i] = h; g_W1lo[i] = l;
    }
    int j = i - H1 * CIN;
    if (j >= 0 && j < H2 * H1) {
        __nv_bfloat16 h, l;
        cvt_hilo(W2[j], h, l);
        g_W2hi[j] = h; g_W2lo[j] = l;
    }
}

// ================= kernel: feat1 -> bf16 hi/lo into A1 cols 256..383 =================
__global__ __launch_bounds__(256) void prep_feat1_kernel(const float* __restrict__ feat1) {
    int i = blockIdx.x * blockDim.x + threadIdx.x;     // one 4-elem chunk
    const int total = M_TOTAL * C1 / 4;
    if (i >= total) return;
    int r = i >> 5;             // C1/4 = 32 chunks per row
    int c4 = (i & 31) * 4;
    float4 v = *(const float4*)(feat1 + (size_t)r * C1 + c4);
    union U4 { uint2 u; __nv_bfloat16 b[4]; } h, l;
    cvt_hilo(v.x, h.b[0], l.b[0]);
    cvt_hilo(v.y, h.b[1], l.b[1]);
    cvt_hilo(v.z, h.b[2], l.b[2]);
    cvt_hilo(v.w, h.b[3], l.b[3]);
    size_t off = (size_t)r * CIN + C2 + c4;
    *(uint2*)(g_A1hi + off) = h.u;
    *(uint2*)(g_A1lo + off) = l.u;
}

// ================= kernel: 3-NN + interpolation (writes bf16 hi/lo) =================
__global__ __launch_bounds__(256) void knn_interp_kernel(
    const float* __restrict__ xyz1,
    const float* __restrict__ xyz2,
    const float* __restrict__ feat2)
{
    __shared__ float4 s_p[SS];
    __shared__ float  s_w[256][3];
    __shared__ int    s_i[256][3];

    const int b   = blockIdx.y;
    const int n0  = blockIdx.x * 256;
    const int tid = threadIdx.x;

    const float* p2 = xyz2 + (size_t)b * SS * 3;
    for (int j = tid; j < SS; j += 256) {
        float x = p2[j * 3 + 0];
        float y = p2[j * 3 + 1];
        float z = p2[j * 3 + 2];
        s_p[j] = make_float4(x, y, z, x * x + y * y + z * z);
    }
    __syncthreads();

    const int   n   = n0 + tid;
    const float* q  = xyz1 + ((size_t)b * NN + n) * 3;
    const float qx = q[0], qy = q[1], qz = q[2];
    const float n1 = qx * qx + qy * qy + qz * qz;
    const float mx = -2.f * qx, my = -2.f * qy, mz = -2.f * qz;

    float d0 = 1e30f, d1 = 1e30f, d2v = 1e30f;
    int   i0 = 0, i1 = 0, i2 = 0;

#pragma unroll 8
    for (int j = 0; j < SS; j++) {
        float4 c = s_p[j];
        float s = fmaf(mx, c.x, fmaf(my, c.y, fmaf(mz, c.z, c.w)));
        if (s < d2v) {
            if (s < d1) {
                d2v = d1; i2 = i1;
                if (s < d0) { d1 = d0; i1 = i0; d0 = s; i0 = j; }
                else        { d1 = s;  i1 = j; }
            } else {
                d2v = s; i2 = j;
            }
        }
    }

    float da = sqrtf(fmaxf(n1 + d0, 0.f)) + 1e-10f;
    float db = sqrtf(fmaxf(n1 + d1, 0.f)) + 1e-10f;
    float dc = sqrtf(fmaxf(n1 + d2v, 0.f)) + 1e-10f;
    float w0 = 1.f / da, w1 = 1.f / db, w2 = 1.f / dc;
    float inv = 1.f / (w0 + w1 + w2);
    s_w[tid][0] = w0 * inv; s_w[tid][1] = w1 * inv; s_w[tid][2] = w2 * inv;
    s_i[tid][0] = i0; s_i[tid][1] = i1; s_i[tid][2] = i2;
    __syncthreads();

    const int lane = tid & 31;
    const int warp = tid >> 5;
    const float4* f2b = (const float4*)(feat2 + (size_t)b * SS * C2);
    for (int pl = warp; pl < 256; pl += 8) {
        const float a0 = s_w[pl][0], a1 = s_w[pl][1], a2 = s_w[pl][2];
        const float4* r0 = f2b + (size_t)s_i[pl][0] * (C2 / 4);
        const float4* r1 = f2b + (size_t)s_i[pl][1] * (C2 / 4);
        const float4* r2 = f2b + (size_t)s_i[pl][2] * (C2 / 4);
        const size_t rowo = (size_t)(b * NN + n0 + pl) * CIN;
#pragma unroll
        for (int c = lane; c < C2 / 4; c += 32) {
            float4 va = r0[c], vb = r1[c], vc = r2[c];
            float o0 = a0 * va.x + a1 * vb.x + a2 * vc.x;
            float o1 = a0 * va.y + a1 * vb.y + a2 * vc.y;
            float o2 = a0 * va.z + a1 * vb.z + a2 * vc.z;
            float o3 = a0 * va.w + a1 * vb.w + a2 * vc.w;
            union U4 { uint2 u; __nv_bfloat16 bv[4]; } h, l;
            cvt_hilo(o0, h.bv[0], l.bv[0]);
            cvt_hilo(o1, h.bv[1], l.bv[1]);
            cvt_hilo(o2, h.bv[2], l.bv[2]);
            cvt_hilo(o3, h.bv[3], l.bv[3]);
            *(uint2*)(g_A1hi + rowo + c * 4) = h.u;
            *(uint2*)(g_A1lo + rowo + c * 4) = l.u;
        }
    }
}

// ================= pure-bf16 cp.async MMA GEMM =================
// Block 256 thr / 8 warps; tile 128x128x32; warp tile 64x32.
// 4-stage ring, 32KB/stage: Ahi 8K | Alo 8K | Bhi 8K | Blo 8K.
// Swizzle: 64B rows (32 bf16), 16B chunk c at c ^ ((row>>1)&3).
#define GEMM_STAGE 32768

template<int GEMM>   // 1: A1 x W1 -> g_y ; 2: A2 x W2 -> out
__global__ void __launch_bounds__(256, 1) gemm_mma_kernel(
    const float* __restrict__ bias,
    float* __restrict__ dest_param)
{
    constexpr int KTOT = (GEMM == 1) ? CIN : H1;
    constexpr int NS   = KTOT / 32;
    constexpr int LDO  = (GEMM == 1) ? H1 : H2;

    extern __shared__ char smem[];
    const uint32_t sb = smem_u32(smem);
    const int tid  = threadIdx.x;
    const int lane = tid & 31;
    const int wid  = tid >> 5;
    const int wm   = wid & 1;
    const int wn   = wid >> 1;
    const int row0 = blockIdx.x * 128;
    const int col0 = blockIdx.y * 128;

    const __nv_bfloat16* Ahi = (GEMM == 1) ? g_A1hi : g_A2hi;
    const __nv_bfloat16* Alo = (GEMM == 1) ? g_A1lo : g_A2lo;
    const __nv_bfloat16* Bhi = (GEMM == 1) ? g_W1hi : g_W2hi;
    const __nv_bfloat16* Blo = (GEMM == 1) ? g_W1lo : g_W2lo;

    // ldmatrix address precompute
    int aoffB[4], asw[4];
#pragma unroll
    for (int mi = 0; mi < 4; mi++) {
        int r = wm * 64 + mi * 16 + (lane & 15);
        aoffB[mi] = r * 64;
        asw[mi]   = (r >> 1) & 3;
    }
    const int asel = lane >> 4;
    int boffB[4], bsw[4];
#pragma unroll
    for (int ni = 0; ni < 4; ni++) {
        int r = wn * 32 + ni * 8 + (lane & 7);
        boffB[ni] = r * 64;
        bsw[ni]   = (r >> 1) & 3;
    }
    const int bsel = (lane >> 3) & 1;

    float acc[4][4][4];
#pragma unroll
    for (int mi = 0; mi < 4; mi++)
#pragma unroll
        for (int ni = 0; ni < 4; ni++)
#pragma unroll
            for (int e = 0; e < 4; e++) acc[mi][ni][e] = 0.f;

    // per-thread cp.async chunk assignment: 8 chunks of 16B per stage
    auto issue_stage = [&](int s) {
        const uint32_t bufa = sb + (uint32_t)(s & 3) * GEMM_STAGE;
        const int k0 = s * 32;
        const __nv_bfloat16* srcs[4] = {
            Ahi + (size_t)row0 * KTOT + k0,
            Alo + (size_t)row0 * KTOT + k0,
            Bhi + (size_t)col0 * KTOT + k0,
            Blo + (size_t)col0 * KTOT + k0
        };
#pragma unroll
        for (int qd = 0; qd < 4; qd++) {
#pragma unroll
            for (int h = 0; h < 2; h++) {
                int chunk = h * 256 + tid;
                int r = chunk >> 2, c = chunk & 3;
                uint32_t dst = bufa + qd * 8192 + r * 64 + ((c ^ ((r >> 1) & 3)) << 4);
                cp16(dst, srcs[qd] + (size_t)r * KTOT + c * 8);
            }
        }
    };

    auto compute_stage = [&](uint32_t bufa) {
#pragma unroll
        for (int k16 = 0; k16 < 2; k16++) {
            uint32_t ah[4][4], al[4][4];
#pragma unroll
            for (int mi = 0; mi < 4; mi++) {
                uint32_t off = aoffB[mi] + ((((k16 * 2 + asel) ^ asw[mi])) << 4);
                ldsm4(ah[mi], bufa + off);
                ldsm4(al[mi], bufa + 8192 + off);
            }
            uint32_t bh[4][2], bl[4][2];
#pragma unroll
            for (int ni = 0; ni < 4; ni++) {
                uint32_t off = boffB[ni] + ((((k16 * 2 + bsel) ^ bsw[ni])) << 4);
                ldsm2(bh[ni], bufa + 16384 + off);
                ldsm2(bl[ni], bufa + 24576 + off);
            }
#pragma unroll
            for (int mi = 0; mi < 4; mi++)
#pragma unroll
                for (int ni = 0; ni < 4; ni++) {
                    mma_bf16(acc[mi][ni], ah[mi], bh[ni]);
                    mma_bf16(acc[mi][ni], ah[mi], bl[ni]);
                    mma_bf16(acc[mi][ni], al[mi], bh[ni]);
                }
        }
    };

    // prologue: 3 stages in flight
    issue_stage(0); CP_COMMIT();
    issue_stage(1); CP_COMMIT();
    issue_stage(2); CP_COMMIT();

#pragma unroll 1
    for (int s = 0; s < NS; s++) {
        CP_WAIT2();            // stage s landed; stages s+1,s+2 in flight
        __syncthreads();       // all threads' chunks visible; all done with buf (s+3)&3
        if (s + 3 < NS) issue_stage(s + 3);
        CP_COMMIT();           // empty commit at tail keeps group count uniform
        compute_stage(sb + (uint32_t)(s & 3) * GEMM_STAGE);
    }

    // ---------------- epilogue: bias + store + channel stats ----------------
    float* dest = (GEMM == 1) ? g_y : dest_param;
    float* gsum = (GEMM == 1) ? g_sum1 : g_sum2;
    float* gsq  = (GEMM == 1) ? g_sumsq1 : g_sumsq2;
    const int g   = lane >> 2;
    const int tig = lane & 3;
#pragma unroll
    for (int ni = 0; ni < 4; ni++) {
        const int col = col0 + wn * 32 + ni * 8 + tig * 2;
        const float b0v = bias[col], b1v = bias[col + 1];
        float s0 = 0.f, s1 = 0.f, q0 = 0.f, q1 = 0.f;
#pragma unroll
        for (int mi = 0; mi < 4; mi++) {
            const int rA = row0 + wm * 64 + mi * 16 + g;
            float v00 = acc[mi][ni][0] + b0v, v01 = acc[mi][ni][1] + b1v;
            float v10 = acc[mi][ni][2] + b0v, v11 = acc[mi][ni][3] + b1v;
            *(float2*)(dest + (size_t)rA * LDO + col)       = make_float2(v00, v01);
            *(float2*)(dest + (size_t)(rA + 8) * LDO + col) = make_float2(v10, v11);
            s0 += v00 + v10; s1 += v01 + v11;
            q0 += v00 * v00 + v10 * v10; q1 += v01 * v01 + v11 * v11;
        }
#pragma unroll
        for (int m = 4; m <= 16; m <<= 1) {
            s0 += __shfl_xor_sync(0xffffffffu, s0, m);
            s1 += __shfl_xor_sync(0xffffffffu, s1, m);
            q0 += __shfl_xor_sync(0xffffffffu, q0, m);
            q1 += __shfl_xor_sync(0xffffffffu, q1, m);
        }
        if (lane < 4) {
            atomicAdd(&gsum[col], s0);
            atomicAdd(&gsum[col + 1], s1);
            atomicAdd(&gsq[col], q0);
            atomicAdd(&gsq[col + 1], q1);
        }
    }
}

// ================= BN finalize kernels =================
__global__ void bn1_finalize_kernel(const float* __restrict__ g1, const float* __restrict__ be1) {
    int c = threadIdx.x;
    if (c < H1) {
        float mean = g_sum1[c] * (1.f / (float)M_TOTAL);
        float var  = g_sumsq1[c] * (1.f / (float)M_TOTAL) - mean * mean;
        float sc   = g1[c] / sqrtf(var + BN_EPS);
        g_scale1[c] = sc;
        g_shift1[c] = be1[c] - mean * sc;
    }
}
__global__ void bn2_finalize_kernel(const float* __restrict__ g2, const float* __restrict__ be2) {
    int c = threadIdx.x;
    if (c < H2) {
        float mean = g_sum2[c] * (1.f / (float)M_TOTAL);
        float var  = g_sumsq2[c] * (1.f / (float)M_TOTAL) - mean * mean;
        float sc   = g2[c] / sqrtf(var + BN_EPS);
        g_scale2[c] = sc;
        g_shift2[c] = be2[c] - mean * sc;
    }
}

// ================= kernel: y -> relu(bn1(y)) as bf16 hi/lo =================
__global__ __launch_bounds__(256) void convert_y_kernel() {
    int i = blockIdx.x * blockDim.x + threadIdx.x;     // one 8-elem chunk
    const int total = M_TOTAL * H1 / 8;
    if (i >= total) return;
    int r  = i >> 5;           // 256/8 = 32 chunks per row
    int c8 = (i & 31) * 8;
    const float* p = g_y + (size_t)r * H1 + c8;
    float4 v0 = *(const float4*)p;
    float4 v1 = *(const float4*)(p + 4);
    float xs[8] = {v0.x, v0.y, v0.z, v0.w, v1.x, v1.y, v1.z, v1.w};
    union U8 { uint4 u; __nv_bfloat16 b[8]; } h, l;
#pragma unroll
    for (int e = 0; e < 8; e++) {
        float x = fmaxf(fmaf(xs[e], g_scale1[c8 + e], g_shift1[c8 + e]), 0.f);
        cvt_hilo(x, h.b[e], l.b[e]);
    }
    size_t off = (size_t)r * H1 + c8;
    *(uint4*)(g_A2hi + off) = h.u;
    *(uint4*)(g_A2lo + off) = l.u;
}

// ================= final BN2 + ReLU in-place =================
__global__ __launch_bounds__(256) void final_bn_kernel(float* __restrict__ out) {
    const int i = blockIdx.x * blockDim.x + threadIdx.x;
    const int total4 = M_TOTAL * H2 / 4;
    if (i < total4) {
        float4 v = ((float4*)out)[i];
        int c = (i * 4) & (H2 - 1);
        v.x = fmaxf(fmaf(v.x, g_scale2[c + 0], g_shift2[c + 0]), 0.f);
        v.y = fmaxf(fmaf(v.y, g_scale2[c + 1], g_shift2[c + 1]), 0.f);
        v.z = fmaxf(fmaf(v.z, g_scale2[c + 2], g_shift2[c + 2]), 0.f);
        v.w = fmaxf(fmaf(v.w, g_scale2[c + 3], g_shift2[c + 3]), 0.f);
        ((float4*)out)[i] = v;
    }
}

// ================= launch =================
extern "C" void kernel_launch(void* const* d_in, const int* in_sizes, int n_in,
                              void* d_out, int out_size)
{
    const float* xyz1  = (const float*)d_in[0];
    const float* xyz2  = (const float*)d_in[1];
    const float* feat1 = (const float*)d_in[2];
    const float* feat2 = (const float*)d_in[3];
    const float* W1    = (const float*)d_in[4];
    const float* b1    = (const float*)d_in[5];
    const float* g1    = (const float*)d_in[6];
    const float* be1   = (const float*)d_in[7];
    const float* W2    = (const float*)d_in[8];
    const float* b2    = (const float*)d_in[9];
    const float* g2    = (const float*)d_in[10];
    const float* be2   = (const float*)d_in[11];
    float* out = (float*)d_out;

    cudaFuncSetAttribute(gemm_mma_kernel<1>, cudaFuncAttributeMaxDynamicSharedMemorySize,
                         4 * GEMM_STAGE);
    cudaFuncSetAttribute(gemm_mma_kernel<2>, cudaFuncAttributeMaxDynamicSharedMemorySize,
                         4 * GEMM_STAGE);

    zero_stats_kernel<<<1, 256>>>();
    prep_weights_kernel<<<(H1 * CIN + H2 * H1 + 255) / 256, 256>>>(W1, W2);
    prep_feat1_kernel<<<(M_TOTAL * C1 / 4 + 255) / 256, 256>>>(feat1);

    dim3 gknn(NN / 256, BB);
    knn_interp_kernel<<<gknn, 256>>>(xyz1, xyz2, feat2);

    gemm_mma_kernel<1><<<dim3(M_TOTAL / 128, H1 / 128), 256, 4 * GEMM_STAGE>>>(b1, nullptr);

    bn1_finalize_kernel<<<1, 256>>>(g1, be1);

    convert_y_kernel<<<(M_TOTAL * H1 / 8 + 255) / 256, 256>>>();

    gemm_mma_kernel<2><<<dim3(M_TOTAL / 128, 1), 256, 4 * GEMM_STAGE>>>(b2, out);

    bn2_finalize_kernel<<<1, 128>>>(g2, be2);

    final_bn_kernel<<<(M_TOTAL * H2 / 4 + 255) / 256, 256>>>(out);
}